// round 16
// baseline (speedup 1.0000x reference)
#include <cuda_runtime.h>
#include <cuda_fp16.h>
#include <cstdint>

// ---------------------------------------------------------------------------
// MLA forward — fp16 HMMA engine + un-absorbed attention (R13 pipeline).
// R15: engine re-tiled for the smem crossbar. Analysis showed the mainloop is
// LDS-byte bound (96KB smem reads per 128x128 k-tile vs 512 HMMA => tensor
// ~40%). New config: 128 threads, 4 warps, 64x64 warp tiles (2x2 grid) =>
// 64KB reads per k-tile (LDS:HMMA 1:1). 2 CTA/SM retained.
// ---------------------------------------------------------------------------

#define BB    4
#define SEQ   2048
#define DIM_  1024
#define NH_   12
#define NOPE_ 128
#define ROPE_ 64
#define QKH_  192
#define VH_   128
#define KVR_  512
#define MTOT  (BB*SEQ)       // 8192
#define KCATW (KVR_+ROPE_)   // 576
#define QKW   (NH_*QKH_ + KCATW)   // 2880
#define HD2   192
#define SM_SCALE_F 0.07216878364870323f

// ------------------------- scratch (static device) -------------------------
__device__ __half g_xh   [MTOT * DIM_];
__device__ __half g_wqkh [QKW * DIM_];
__device__ __half g_wbh  [NH_ * 256 * KVR_];
__device__ __half g_woh  [DIM_ * (NH_*VH_)];
__device__ __half g_qkraw[MTOT * QKW];          // pe cols pre-roped by EPI=3
__device__ __half g_kcat [MTOT * KCATW];        // only cols 0..511 used
__device__ __half g_kcath[(size_t)BB * NH_ * SEQ * HD2];
__device__ __half g_vT   [(size_t)BB * NH_ * VH_ * SEQ];
__device__ __half g_scores[(size_t)BB*NH_*SEQ*SEQ];
__device__ __half g_o2   [MTOT * NH_*VH_];
__device__ float  g_rsum [BB*NH_*SEQ];

// ------------------------------- helpers -----------------------------------
__device__ __forceinline__ uint32_t smem_u32(const void* p) {
    uint32_t a;
    asm("{ .reg .u64 t; cvta.to.shared.u64 t, %1; cvt.u32.u64 %0, t; }" : "=r"(a) : "l"(p));
    return a;
}
__device__ __forceinline__ void cp16(uint32_t dst, const void* src, bool pred) {
    int sz = pred ? 16 : 0;
    asm volatile("cp.async.cg.shared.global [%0], [%1], 16, %2;\n"
                 :: "r"(dst), "l"(src), "r"(sz));
}
#define CP_COMMIT() asm volatile("cp.async.commit_group;\n" ::: "memory")
#define CP_WAIT(N)  asm volatile("cp.async.wait_group %0;\n" :: "n"(N) : "memory")

#define HMMA16816(d, a0, a1, a2, a3, b0, b1) \
    asm volatile("mma.sync.aligned.m16n8k16.row.col.f32.f16.f16.f32 " \
        "{%0,%1,%2,%3}, {%4,%5,%6,%7}, {%8,%9}, {%0,%1,%2,%3};" \
        : "+f"((d)[0]), "+f"((d)[1]), "+f"((d)[2]), "+f"((d)[3]) \
        : "r"(a0), "r"(a1), "r"(a2), "r"(a3), "r"(b0), "r"(b1))

// ---------------------------- fp16 MMA GEMM --------------------------------
// C[M,N] = alpha * A @ B^T.  A [M,K] lda halfs, B [N,K] ldb halfs.
// Tile 128x128, BK=64, 3-stage cp.async, 128 threads (4 warps, 64x64 warp
// tiles, 2x2 warp grid), 2 CTAs/SM.
// EPI: 0 plain, 1 exp+causal+rowsum, 2 normalize by rowsum,
//      3 plain + inline RoPE on q_pe columns (frq = freqs table).
#define PITCH32 36
#define PITCHB  144
#define STG_B   (128 * PITCHB)
#define STAGEB  (2 * STG_B)
#define SMEMB   (3 * STAGEB)             // 110592 B

template<int EPI, bool CSKIP, bool CLIMK, typename OutT>
__global__ __launch_bounds__(128, 2)
void hgemm(const __half* __restrict__ A, const __half* __restrict__ B,
           OutT* __restrict__ C,
           int M, int N, int K, int lda, int ldb, int ldc,
           int zdiv,
           long long sAo, long long sAi, long long sBo, long long sBi,
           long long sCo, long long sCi,
           float alpha, float* __restrict__ rsum, int rs_stride,
           const float* __restrict__ frq)
{
    extern __shared__ char smem[];
    int z  = blockIdx.z;
    int zo = z / zdiv, zi = z - zo * zdiv;
    A += zo * sAo + zi * sAi;
    B += zo * sBo + zi * sBi;
    C += zo * sCo + zi * sCi;
    if (EPI == 1 || EPI == 2) rsum += (long long)z * rs_stride;

    int m0 = blockIdx.y * 128;
    int n0 = blockIdx.x * 128;
    if (CSKIP && n0 > m0 + 127) return;
    int kend = CLIMK ? min(K, m0 + 128) : K;
    int nt = kend >> 6;

    int tid  = threadIdx.x;
    int lane = tid & 31, warp = tid >> 5;
    int wm = (warp & 1) * 64;            // 2 warps along M
    int wn = (warp >> 1) * 64;           // 2 warps along N
    int g  = lane >> 2, t = lane & 3;

    uint32_t sbase = smem_u32(smem);

    auto load_stage = [&](int s, int k0) {
        uint32_t sA = sbase + (uint32_t)(s * STAGEB);
        uint32_t sB = sA + STG_B;
#pragma unroll
        for (int i = 0; i < 8; i++) {
            int idx = tid + i * 128;
            int row = idx >> 3, c16 = idx & 7;
            uint32_t doff = (uint32_t)(row * PITCHB + c16 * 16);
            cp16(sA + doff, A + (long long)(m0 + row) * lda + k0 + c16 * 8, true);
            int rb = n0 + row;
            const __half* srcB = B + (long long)(rb < N ? rb : 0) * ldb + k0 + c16 * 8;
            cp16(sB + doff, srcB, rb < N);
        }
        CP_COMMIT();
    };

    float acc[4][8][4];
#pragma unroll
    for (int mi = 0; mi < 4; mi++)
#pragma unroll
        for (int ni = 0; ni < 8; ni++)
#pragma unroll
            for (int c = 0; c < 4; c++) acc[mi][ni][c] = 0.f;

    load_stage(0, 0);
    if (nt > 1) load_stage(1, 64);

    int stage = 0;
    for (int kt = 0; kt < nt; kt++) {
        if (kt + 1 < nt) { CP_WAIT(1); } else { CP_WAIT(0); }
        __syncthreads();

        if (kt + 2 < nt) {
            int ns = stage + 2; if (ns >= 3) ns -= 3;
            load_stage(ns, (kt + 2) << 6);
        }

        const uint32_t* As = (const uint32_t*)(smem + stage * STAGEB);
        const uint32_t* Bs = (const uint32_t*)(smem + stage * STAGEB + STG_B);

#pragma unroll
        for (int ks = 0; ks < 4; ks++) {
            int kb = ks * 8;
            uint32_t af[4][4];
#pragma unroll
            for (int mi = 0; mi < 4; mi++) {
                int r = wm + mi * 16 + g;
                af[mi][0] = As[r * PITCH32 + kb + t];
                af[mi][1] = As[(r + 8) * PITCH32 + kb + t];
                af[mi][2] = As[r * PITCH32 + kb + t + 4];
                af[mi][3] = As[(r + 8) * PITCH32 + kb + t + 4];
            }
            uint32_t bf[8][2];
#pragma unroll
            for (int ni = 0; ni < 8; ni++) {
                int rn = wn + ni * 8 + g;
                bf[ni][0] = Bs[rn * PITCH32 + kb + t];
                bf[ni][1] = Bs[rn * PITCH32 + kb + t + 4];
            }
#pragma unroll
            for (int mi = 0; mi < 4; mi++)
#pragma unroll
                for (int ni = 0; ni < 8; ni++)
                    HMMA16816(acc[mi][ni], af[mi][0], af[mi][1], af[mi][2], af[mi][3],
                              bf[ni][0], bf[ni][1]);
        }
        stage++; if (stage == 3) stage = 0;
    }

    // ---------------------------- epilogue ----------------------------
    float rinv[4][2];
    if (EPI == 2) {
#pragma unroll
        for (int mi = 0; mi < 4; mi++)
#pragma unroll
            for (int h2 = 0; h2 < 2; h2++)
                rinv[mi][h2] = 1.f / rsum[m0 + wm + mi * 16 + g + h2 * 8];
    }
    float rs[4][2] = {{0.f,0.f},{0.f,0.f},{0.f,0.f},{0.f,0.f}};
#pragma unroll
    for (int mi = 0; mi < 4; mi++) {
#pragma unroll
        for (int h2 = 0; h2 < 2; h2++) {
            int grow = m0 + wm + mi * 16 + g + h2 * 8;
            OutT* crow = C + (long long)grow * ldc;
#pragma unroll
            for (int ni = 0; ni < 8; ni++) {
                int col = n0 + wn + ni * 8 + 2 * t;
                if (col >= N) continue;
                float v0 = acc[mi][ni][h2 * 2 + 0];
                float v1 = acc[mi][ni][h2 * 2 + 1];
                if (EPI == 0) {
                    v0 *= alpha; v1 *= alpha;
                } else if (EPI == 1) {
                    v0 = (col     <= grow) ? __expf(v0 * alpha) : 0.f;
                    v1 = (col + 1 <= grow) ? __expf(v1 * alpha) : 0.f;
                } else if (EPI == 2) {
                    v0 *= rinv[mi][h2]; v1 *= rinv[mi][h2];
                } else {
                    // EPI==3: proj GEMM — inline RoPE on q_pe columns.
                    int ch = col % QKH_;
                    if (col < NH_*QKH_ && ch >= NOPE_) {
                        int s = grow & (SEQ - 1);
                        const float* f = frq + s * ROPE_ + (ch - NOPE_);
                        float c = f[0], si = f[1];
                        float nr  = v0 * c - v1 * si;
                        float nim = v0 * si + v1 * c;
                        v0 = nr; v1 = nim;
                    }
                }
                if (sizeof(OutT) == 2) {
                    __half2 h = __floats2half2_rn(v0, v1);
                    if (EPI == 1) {   // rowsum must match stored (rounded) P
                        float2 hr = __half22float2(h);
                        rs[mi][h2] += hr.x + hr.y;
                    }
                    if (col + 1 < N) *(__half2*)((__half*)crow + col) = h;
                    else             ((__half*)crow)[col] = __low2half(h);
                } else {
                    if (col + 1 < N) *(float2*)((float*)crow + col) = make_float2(v0, v1);
                    else             ((float*)crow)[col] = v0;
                }
            }
        }
    }
    if (EPI == 1) {
#pragma unroll
        for (int mi = 0; mi < 4; mi++)
#pragma unroll
            for (int h2 = 0; h2 < 2; h2++) {
                float s = rs[mi][h2];
                s += __shfl_xor_sync(0xffffffffu, s, 1);
                s += __shfl_xor_sync(0xffffffffu, s, 2);
                if (t == 0)
                    atomicAdd(&rsum[m0 + wm + mi * 16 + g + h2 * 8], s);
            }
    }
}

// ------------------------------ prep kernel --------------------------------
#define N4_X   (MTOT*DIM_/4)
#define N4_WQ  ((NH_*QKH_)*DIM_/4)
#define N4_WA  (KCATW*DIM_/4)
#define N4_WB  (NH_*256*KVR_/4)
#define N4_WO  (DIM_*(NH_*VH_)/4)
#define N4_RS  (BB*NH_*SEQ/4)
#define N4_TOT (N4_X+N4_WQ+N4_WA+N4_WB+N4_WO+N4_RS)

__global__ void prep_all(const float* __restrict__ x,  const float* __restrict__ wq,
                         const float* __restrict__ wa, const float* __restrict__ wb,
                         const float* __restrict__ wo,
                         __half* __restrict__ xh, __half* __restrict__ wqkh,
                         __half* __restrict__ wbh, __half* __restrict__ woh,
                         float* __restrict__ rsum)
{
    long long u = (long long)blockIdx.x * blockDim.x + threadIdx.x;
    if (u >= N4_TOT) return;
    const float* src; __half* dst;
    if (u < N4_X)                       { src = x;  dst = xh; }
    else if ((u -= N4_X)  < N4_WQ)      { src = wq; dst = wqkh; }
    else if ((u -= N4_WQ) < N4_WA)      { src = wa; dst = wqkh + (long long)(NH_*QKH_)*DIM_; }
    else if ((u -= N4_WA) < N4_WB)      { src = wb; dst = wbh; }
    else if ((u -= N4_WB) < N4_WO)      { src = wo; dst = woh; }
    else { u -= N4_WO; *(float4*)(rsum + u * 4) = make_float4(0.f,0.f,0.f,0.f); return; }
    long long i = u * 4;
    float4 v = *(const float4*)(src + i);
    *(__half2*)(dst + i)     = __floats2half2_rn(v.x, v.y);
    *(__half2*)(dst + i + 2) = __floats2half2_rn(v.z, v.w);
}

// --------------------- rmsnorm + k_pe scatter into kcath -------------------
__global__ void rmsnorm_rope_k_kernel(const __half* __restrict__ qkraw,
                                      const float* __restrict__ w,
                                      const float* __restrict__ freqs,
                                      __half* __restrict__ kcat,
                                      __half* __restrict__ kcath)
{
    int m = blockIdx.x;
    const __half* src = qkraw + (long long)m * QKW + (NH_*QKH_);
    __half*       dst = kcat  + (long long)m * KCATW;
    int tid = threadIdx.x;

    float ss = 0.f;
#pragma unroll
    for (int c = tid; c < KVR_; c += 128) { float v = __half2float(src[c]); ss += v * v; }
#pragma unroll
    for (int o = 16; o; o >>= 1) ss += __shfl_xor_sync(0xffffffffu, ss, o);
    __shared__ float r4[4];
    if ((tid & 31) == 0) r4[tid >> 5] = ss;
    __syncthreads();
    float tot = r4[0] + r4[1] + r4[2] + r4[3];
    float scale = rsqrtf(tot / (float)KVR_ + 1e-6f);

#pragma unroll
    for (int c = tid; c < KVR_; c += 128)
        dst[c] = __float2half_rn(__half2float(src[c]) * scale * w[c]);

    if (tid < ROPE_ / 2) {
        int s = m & (SEQ - 1);
        int b = m >> 11;
        float r0 = __half2float(src[KVR_ + 2 * tid]);
        float r1 = __half2float(src[KVR_ + 2 * tid + 1]);
        float fr = freqs[s * ROPE_ + 2 * tid];
        float fi = freqs[s * ROPE_ + 2 * tid + 1];
        __half2 pe = __floats2half2_rn(r0 * fr - r1 * fi, r0 * fi + r1 * fr);
#pragma unroll
        for (int h = 0; h < NH_; h++)
            *(__half2*)(kcath + ((long long)(b * NH_ + h) * SEQ + s) * HD2 + NOPE_ + 2 * tid) = pe;
    }
}

// -------------------------------- launcher ---------------------------------
extern "C" void kernel_launch(void* const* d_in, const int* in_sizes, int n_in,
                              void* d_out, int out_size)
{
    const float* x      = (const float*)d_in[0];
    const float* wq     = (const float*)d_in[1];
    const float* wkv_a  = (const float*)d_in[2];
    const float* knw    = (const float*)d_in[3];
    const float* wkv_b  = (const float*)d_in[4];
    const float* wo     = (const float*)d_in[5];
    const float* freqs  = (const float*)d_in[6];
    float* out = (float*)d_out;

    __half *xh,*wqkh,*wbh,*woh,*qkraw,*kcat,*kcath,*vT,*scores,*o2;
    float *rsum;
    cudaGetSymbolAddress((void**)&xh,    g_xh);
    cudaGetSymbolAddress((void**)&wqkh,  g_wqkh);
    cudaGetSymbolAddress((void**)&wbh,   g_wbh);
    cudaGetSymbolAddress((void**)&woh,   g_woh);
    cudaGetSymbolAddress((void**)&qkraw, g_qkraw);
    cudaGetSymbolAddress((void**)&kcat,  g_kcat);
    cudaGetSymbolAddress((void**)&kcath, g_kcath);
    cudaGetSymbolAddress((void**)&vT,    g_vT);
    cudaGetSymbolAddress((void**)&scores,g_scores);
    cudaGetSymbolAddress((void**)&o2,    g_o2);
    cudaGetSymbolAddress((void**)&rsum,  g_rsum);

    cudaFuncSetAttribute(hgemm<3,false,false,__half>, cudaFuncAttributeMaxDynamicSharedMemorySize, SMEMB);
    cudaFuncSetAttribute(hgemm<0,false,false,__half>, cudaFuncAttributeMaxDynamicSharedMemorySize, SMEMB);
    cudaFuncSetAttribute(hgemm<1,true ,false,__half>, cudaFuncAttributeMaxDynamicSharedMemorySize, SMEMB);
    cudaFuncSetAttribute(hgemm<2,false,true ,__half>, cudaFuncAttributeMaxDynamicSharedMemorySize, SMEMB);
    cudaFuncSetAttribute(hgemm<0,false,false,float >, cudaFuncAttributeMaxDynamicSharedMemorySize, SMEMB);

    // 1) prep: all conversions + rsum zero
    prep_all<<<(N4_TOT + 255)/256, 256>>>(x, wq, wkv_a, wkv_b, wo,
                                          xh, wqkh, wbh, woh, rsum);

    // 2) [q | kv] = x @ [wq ; wkv_a].T with inline q_pe RoPE (EPI=3)
    hgemm<3,false,false,__half><<<dim3(23,64,1),128,SMEMB>>>(xh, wqkh, qkraw,
        MTOT, QKW, DIM_, DIM_, DIM_, QKW,
        1, 0,0, 0,0, 0,0, 1.f, nullptr, 0, freqs);

    // 3) kcat[:,0:512] = rmsnorm(kv_c); k_pe roped + scattered into kcath x12
    rmsnorm_rope_k_kernel<<<MTOT,128>>>(qkraw, knw, freqs, kcat, kcath);

    // 4) kcath[b,h,:, :128] = kv_c @ Wb_nope_h^T
    hgemm<0,false,false,__half><<<dim3(1,16,BB*NH_),128,SMEMB>>>(kcat, wbh, kcath,
        SEQ, NOPE_, KVR_, KCATW, KVR_, HD2,
        NH_,
        (long long)SEQ*KCATW,    0,
        0,                       (long long)256*KVR_,
        (long long)NH_*SEQ*HD2,  (long long)SEQ*HD2,
        1.f, nullptr, 0, nullptr);

    // 5) vT[b,h] = Wb_v_h @ kv_c^T
    hgemm<0,false,false,__half><<<dim3(16,1,BB*NH_),128,SMEMB>>>(
        wbh + (long long)NOPE_*KVR_, kcat, vT,
        VH_, SEQ, KVR_, KVR_, KCATW, SEQ,
        NH_,
        0,                       (long long)256*KVR_,
        (long long)SEQ*KCATW,    0,
        (long long)NH_*VH_*SEQ,  (long long)VH_*SEQ,
        1.f, nullptr, 0, nullptr);

    // 6) P = exp(SM_SCALE * q_h @ kcath^T) causal + row sums  (A = qkraw)
    hgemm<1,true,false,__half><<<dim3(16,16,BB*NH_),128,SMEMB>>>(qkraw, kcath, scores,
        SEQ, SEQ, HD2, QKW, HD2, SEQ,
        NH_,
        (long long)SEQ*QKW,      (long long)QKH_,
        (long long)NH_*SEQ*HD2,  (long long)SEQ*HD2,
        (long long)NH_*SEQ*SEQ,  (long long)SEQ*SEQ,
        SM_SCALE_F, rsum, SEQ, nullptr);

    // 7) o2[b,s,h,:] = (P @ vT_h^T) / rowsum   (causal K-limit)
    hgemm<2,false,true,__half><<<dim3(1,16,BB*NH_),128,SMEMB>>>(scores, vT, o2,
        SEQ, VH_, SEQ, SEQ, SEQ, NH_*VH_,
        NH_,
        (long long)NH_*SEQ*SEQ,  (long long)SEQ*SEQ,
        (long long)NH_*VH_*SEQ,  (long long)VH_*SEQ,
        (long long)SEQ*NH_*VH_,  (long long)VH_,
        1.f, rsum, SEQ, nullptr);

    // 8) out = o2 @ wo.T   (fp32 output)
    hgemm<0,false,false,float><<<dim3(8,64,1),128,SMEMB>>>(o2, woh, out,
        MTOT, DIM_, NH_*VH_, NH_*VH_, NH_*VH_, DIM_,
        1, 0,0, 0,0, 0,0, 1.f, nullptr, 0, nullptr);
}

// round 17
// speedup vs baseline: 1.6858x; 1.6858x over previous
#include <cuda_runtime.h>
#include <cuda_fp16.h>
#include <cstdint>

// ---------------------------------------------------------------------------
// MLA forward — fp16 HMMA engine + un-absorbed attention (R13 pipeline,
// restored after R15 regression: 256 threads, 32x64 warp tiles, 3-stage
// cp.async, 2 CTA/SM is the register-file-limited optimum).
// R16 delta: scores epilogue uses exp2f with log2(e) folded into alpha
// (removes 64 FMULs/thread from the MUFU-serialized epilogue).
// ---------------------------------------------------------------------------

#define BB    4
#define SEQ   2048
#define DIM_  1024
#define NH_   12
#define NOPE_ 128
#define ROPE_ 64
#define QKH_  192
#define VH_   128
#define KVR_  512
#define MTOT  (BB*SEQ)       // 8192
#define KCATW (KVR_+ROPE_)   // 576
#define QKW   (NH_*QKH_ + KCATW)   // 2880
#define HD2   192
#define SM_SCALE_F 0.07216878364870323f
#define SM_SCALE_L2E 0.10412927605186013f   // SM_SCALE * log2(e)

// ------------------------- scratch (static device) -------------------------
__device__ __half g_xh   [MTOT * DIM_];
__device__ __half g_wqkh [QKW * DIM_];
__device__ __half g_wbh  [NH_ * 256 * KVR_];
__device__ __half g_woh  [DIM_ * (NH_*VH_)];
__device__ __half g_qkraw[MTOT * QKW];          // pe cols pre-roped by EPI=3
__device__ __half g_kcat [MTOT * KCATW];        // only cols 0..511 used
__device__ __half g_kcath[(size_t)BB * NH_ * SEQ * HD2];
__device__ __half g_vT   [(size_t)BB * NH_ * VH_ * SEQ];
__device__ __half g_scores[(size_t)BB*NH_*SEQ*SEQ];
__device__ __half g_o2   [MTOT * NH_*VH_];
__device__ float  g_rsum [BB*NH_*SEQ];

// ------------------------------- helpers -----------------------------------
__device__ __forceinline__ uint32_t smem_u32(const void* p) {
    uint32_t a;
    asm("{ .reg .u64 t; cvta.to.shared.u64 t, %1; cvt.u32.u64 %0, t; }" : "=r"(a) : "l"(p));
    return a;
}
__device__ __forceinline__ void cp16(uint32_t dst, const void* src, bool pred) {
    int sz = pred ? 16 : 0;
    asm volatile("cp.async.cg.shared.global [%0], [%1], 16, %2;\n"
                 :: "r"(dst), "l"(src), "r"(sz));
}
#define CP_COMMIT() asm volatile("cp.async.commit_group;\n" ::: "memory")
#define CP_WAIT(N)  asm volatile("cp.async.wait_group %0;\n" :: "n"(N) : "memory")

#define HMMA16816(d, a0, a1, a2, a3, b0, b1) \
    asm volatile("mma.sync.aligned.m16n8k16.row.col.f32.f16.f16.f32 " \
        "{%0,%1,%2,%3}, {%4,%5,%6,%7}, {%8,%9}, {%0,%1,%2,%3};" \
        : "+f"((d)[0]), "+f"((d)[1]), "+f"((d)[2]), "+f"((d)[3]) \
        : "r"(a0), "r"(a1), "r"(a2), "r"(a3), "r"(b0), "r"(b1))

// ---------------------------- fp16 MMA GEMM --------------------------------
// C[M,N] = alpha * A @ B^T.  A [M,K] lda halfs, B [N,K] ldb halfs.
// Tile 128x128, BK=64, 3-stage cp.async, 256 threads (8 warps, 32x64 warp
// tiles, 4x2 grid), 2 CTAs/SM.
// EPI: 0 plain, 1 exp2(alpha*S)+causal+rowsum, 2 normalize by rowsum,
//      3 plain + inline RoPE on q_pe columns (frq = freqs table).
#define PITCH32 36
#define PITCHB  144
#define STG_B   (128 * PITCHB)
#define STAGEB  (2 * STG_B)
#define SMEMB   (3 * STAGEB)             // 110592 B

template<int EPI, bool CSKIP, bool CLIMK, typename OutT>
__global__ __launch_bounds__(256, 2)
void hgemm(const __half* __restrict__ A, const __half* __restrict__ B,
           OutT* __restrict__ C,
           int M, int N, int K, int lda, int ldb, int ldc,
           int zdiv,
           long long sAo, long long sAi, long long sBo, long long sBi,
           long long sCo, long long sCi,
           float alpha, float* __restrict__ rsum, int rs_stride,
           const float* __restrict__ frq)
{
    extern __shared__ char smem[];
    int z  = blockIdx.z;
    int zo = z / zdiv, zi = z - zo * zdiv;
    A += zo * sAo + zi * sAi;
    B += zo * sBo + zi * sBi;
    C += zo * sCo + zi * sCi;
    if (EPI == 1 || EPI == 2) rsum += (long long)z * rs_stride;

    int m0 = blockIdx.y * 128;
    int n0 = blockIdx.x * 128;
    if (CSKIP && n0 > m0 + 127) return;
    int kend = CLIMK ? min(K, m0 + 128) : K;
    int nt = kend >> 6;

    int tid  = threadIdx.x;
    int lane = tid & 31, warp = tid >> 5;
    int wm = (warp & 3) * 32;
    int wn = (warp >> 2) * 64;
    int g  = lane >> 2, t = lane & 3;

    uint32_t sbase = smem_u32(smem);
    int ldrow = tid >> 3;
    int ldc16 = tid & 7;

    auto load_stage = [&](int s, int k0) {
        uint32_t sA = sbase + (uint32_t)(s * STAGEB);
        uint32_t sB = sA + STG_B;
#pragma unroll
        for (int i = 0; i < 4; i++) {
            int row = ldrow + i * 32;
            uint32_t doff = (uint32_t)(row * PITCHB + ldc16 * 16);
            cp16(sA + doff, A + (long long)(m0 + row) * lda + k0 + ldc16 * 8, true);
            int rb = n0 + row;
            const __half* srcB = B + (long long)(rb < N ? rb : 0) * ldb + k0 + ldc16 * 8;
            cp16(sB + doff, srcB, rb < N);
        }
        CP_COMMIT();
    };

    float acc[2][8][4];
#pragma unroll
    for (int mi = 0; mi < 2; mi++)
#pragma unroll
        for (int ni = 0; ni < 8; ni++)
#pragma unroll
            for (int c = 0; c < 4; c++) acc[mi][ni][c] = 0.f;

    load_stage(0, 0);
    if (nt > 1) load_stage(1, 64);

    int stage = 0;
    for (int kt = 0; kt < nt; kt++) {
        if (kt + 1 < nt) { CP_WAIT(1); } else { CP_WAIT(0); }
        __syncthreads();

        if (kt + 2 < nt) {
            int ns = stage + 2; if (ns >= 3) ns -= 3;
            load_stage(ns, (kt + 2) << 6);
        }

        const uint32_t* As = (const uint32_t*)(smem + stage * STAGEB);
        const uint32_t* Bs = (const uint32_t*)(smem + stage * STAGEB + STG_B);

#pragma unroll
        for (int ks = 0; ks < 4; ks++) {
            int kb = ks * 8;
            uint32_t af[2][4];
#pragma unroll
            for (int mi = 0; mi < 2; mi++) {
                int r = wm + mi * 16 + g;
                af[mi][0] = As[r * PITCH32 + kb + t];
                af[mi][1] = As[(r + 8) * PITCH32 + kb + t];
                af[mi][2] = As[r * PITCH32 + kb + t + 4];
                af[mi][3] = As[(r + 8) * PITCH32 + kb + t + 4];
            }
            uint32_t bf[8][2];
#pragma unroll
            for (int ni = 0; ni < 8; ni++) {
                int rn = wn + ni * 8 + g;
                bf[ni][0] = Bs[rn * PITCH32 + kb + t];
                bf[ni][1] = Bs[rn * PITCH32 + kb + t + 4];
            }
#pragma unroll
            for (int mi = 0; mi < 2; mi++)
#pragma unroll
                for (int ni = 0; ni < 8; ni++)
                    HMMA16816(acc[mi][ni], af[mi][0], af[mi][1], af[mi][2], af[mi][3],
                              bf[ni][0], bf[ni][1]);
        }
        stage++; if (stage == 3) stage = 0;
    }

    // ---------------------------- epilogue ----------------------------
    float rinv[2][2];
    if (EPI == 2) {
#pragma unroll
        for (int mi = 0; mi < 2; mi++)
#pragma unroll
            for (int h2 = 0; h2 < 2; h2++)
                rinv[mi][h2] = 1.f / rsum[m0 + wm + mi * 16 + g + h2 * 8];
    }
    float rs[2][2] = {{0.f, 0.f}, {0.f, 0.f}};
#pragma unroll
    for (int mi = 0; mi < 2; mi++) {
#pragma unroll
        for (int h2 = 0; h2 < 2; h2++) {
            int grow = m0 + wm + mi * 16 + g + h2 * 8;
            OutT* crow = C + (long long)grow * ldc;
#pragma unroll
            for (int ni = 0; ni < 8; ni++) {
                int col = n0 + wn + ni * 8 + 2 * t;
                if (col >= N) continue;
                float v0 = acc[mi][ni][h2 * 2 + 0];
                float v1 = acc[mi][ni][h2 * 2 + 1];
                if (EPI == 0) {
                    v0 *= alpha; v1 *= alpha;
                } else if (EPI == 1) {
                    // alpha already includes log2(e): exp(s*scale)=exp2(s*alpha)
                    v0 = (col     <= grow) ? exp2f(v0 * alpha) : 0.f;
                    v1 = (col + 1 <= grow) ? exp2f(v1 * alpha) : 0.f;
                } else if (EPI == 2) {
                    v0 *= rinv[mi][h2]; v1 *= rinv[mi][h2];
                } else {
                    // EPI==3: proj GEMM — inline RoPE on q_pe columns.
                    int ch = col % QKH_;
                    if (col < NH_*QKH_ && ch >= NOPE_) {
                        int s = grow & (SEQ - 1);
                        const float* f = frq + s * ROPE_ + (ch - NOPE_);
                        float c = f[0], si = f[1];
                        float nr  = v0 * c - v1 * si;
                        float nim = v0 * si + v1 * c;
                        v0 = nr; v1 = nim;
                    }
                }
                if (sizeof(OutT) == 2) {
                    __half2 h = __floats2half2_rn(v0, v1);
                    if (EPI == 1) {   // rowsum must match stored (rounded) P
                        float2 hr = __half22float2(h);
                        rs[mi][h2] += hr.x + hr.y;
                    }
                    if (col + 1 < N) *(__half2*)((__half*)crow + col) = h;
                    else             ((__half*)crow)[col] = __low2half(h);
                } else {
                    if (col + 1 < N) *(float2*)((float*)crow + col) = make_float2(v0, v1);
                    else             ((float*)crow)[col] = v0;
                }
            }
        }
    }
    if (EPI == 1) {
#pragma unroll
        for (int mi = 0; mi < 2; mi++)
#pragma unroll
            for (int h2 = 0; h2 < 2; h2++) {
                float s = rs[mi][h2];
                s += __shfl_xor_sync(0xffffffffu, s, 1);
                s += __shfl_xor_sync(0xffffffffu, s, 2);
                if (t == 0)
                    atomicAdd(&rsum[m0 + wm + mi * 16 + g + h2 * 8], s);
            }
    }
}

// ------------------------------ prep kernel --------------------------------
#define N4_X   (MTOT*DIM_/4)
#define N4_WQ  ((NH_*QKH_)*DIM_/4)
#define N4_WA  (KCATW*DIM_/4)
#define N4_WB  (NH_*256*KVR_/4)
#define N4_WO  (DIM_*(NH_*VH_)/4)
#define N4_RS  (BB*NH_*SEQ/4)
#define N4_TOT (N4_X+N4_WQ+N4_WA+N4_WB+N4_WO+N4_RS)

__global__ void prep_all(const float* __restrict__ x,  const float* __restrict__ wq,
                         const float* __restrict__ wa, const float* __restrict__ wb,
                         const float* __restrict__ wo,
                         __half* __restrict__ xh, __half* __restrict__ wqkh,
                         __half* __restrict__ wbh, __half* __restrict__ woh,
                         float* __restrict__ rsum)
{
    long long u = (long long)blockIdx.x * blockDim.x + threadIdx.x;
    if (u >= N4_TOT) return;
    const float* src; __half* dst;
    if (u < N4_X)                       { src = x;  dst = xh; }
    else if ((u -= N4_X)  < N4_WQ)      { src = wq; dst = wqkh; }
    else if ((u -= N4_WQ) < N4_WA)      { src = wa; dst = wqkh + (long long)(NH_*QKH_)*DIM_; }
    else if ((u -= N4_WA) < N4_WB)      { src = wb; dst = wbh; }
    else if ((u -= N4_WB) < N4_WO)      { src = wo; dst = woh; }
    else { u -= N4_WO; *(float4*)(rsum + u * 4) = make_float4(0.f,0.f,0.f,0.f); return; }
    long long i = u * 4;
    float4 v = *(const float4*)(src + i);
    *(__half2*)(dst + i)     = __floats2half2_rn(v.x, v.y);
    *(__half2*)(dst + i + 2) = __floats2half2_rn(v.z, v.w);
}

// --------------------- rmsnorm + k_pe scatter into kcath -------------------
__global__ void rmsnorm_rope_k_kernel(const __half* __restrict__ qkraw,
                                      const float* __restrict__ w,
                                      const float* __restrict__ freqs,
                                      __half* __restrict__ kcat,
                                      __half* __restrict__ kcath)
{
    int m = blockIdx.x;
    const __half* src = qkraw + (long long)m * QKW + (NH_*QKH_);
    __half*       dst = kcat  + (long long)m * KCATW;
    int tid = threadIdx.x;

    float ss = 0.f;
#pragma unroll
    for (int c = tid; c < KVR_; c += 128) { float v = __half2float(src[c]); ss += v * v; }
#pragma unroll
    for (int o = 16; o; o >>= 1) ss += __shfl_xor_sync(0xffffffffu, ss, o);
    __shared__ float r4[4];
    if ((tid & 31) == 0) r4[tid >> 5] = ss;
    __syncthreads();
    float tot = r4[0] + r4[1] + r4[2] + r4[3];
    float scale = rsqrtf(tot / (float)KVR_ + 1e-6f);

#pragma unroll
    for (int c = tid; c < KVR_; c += 128)
        dst[c] = __float2half_rn(__half2float(src[c]) * scale * w[c]);

    if (tid < ROPE_ / 2) {
        int s = m & (SEQ - 1);
        int b = m >> 11;
        float r0 = __half2float(src[KVR_ + 2 * tid]);
        float r1 = __half2float(src[KVR_ + 2 * tid + 1]);
        float fr = freqs[s * ROPE_ + 2 * tid];
        float fi = freqs[s * ROPE_ + 2 * tid + 1];
        __half2 pe = __floats2half2_rn(r0 * fr - r1 * fi, r0 * fi + r1 * fr);
#pragma unroll
        for (int h = 0; h < NH_; h++)
            *(__half2*)(kcath + ((long long)(b * NH_ + h) * SEQ + s) * HD2 + NOPE_ + 2 * tid) = pe;
    }
}

// -------------------------------- launcher ---------------------------------
extern "C" void kernel_launch(void* const* d_in, const int* in_sizes, int n_in,
                              void* d_out, int out_size)
{
    const float* x      = (const float*)d_in[0];
    const float* wq     = (const float*)d_in[1];
    const float* wkv_a  = (const float*)d_in[2];
    const float* knw    = (const float*)d_in[3];
    const float* wkv_b  = (const float*)d_in[4];
    const float* wo     = (const float*)d_in[5];
    const float* freqs  = (const float*)d_in[6];
    float* out = (float*)d_out;

    __half *xh,*wqkh,*wbh,*woh,*qkraw,*kcat,*kcath,*vT,*scores,*o2;
    float *rsum;
    cudaGetSymbolAddress((void**)&xh,    g_xh);
    cudaGetSymbolAddress((void**)&wqkh,  g_wqkh);
    cudaGetSymbolAddress((void**)&wbh,   g_wbh);
    cudaGetSymbolAddress((void**)&woh,   g_woh);
    cudaGetSymbolAddress((void**)&qkraw, g_qkraw);
    cudaGetSymbolAddress((void**)&kcat,  g_kcat);
    cudaGetSymbolAddress((void**)&kcath, g_kcath);
    cudaGetSymbolAddress((void**)&vT,    g_vT);
    cudaGetSymbolAddress((void**)&scores,g_scores);
    cudaGetSymbolAddress((void**)&o2,    g_o2);
    cudaGetSymbolAddress((void**)&rsum,  g_rsum);

    cudaFuncSetAttribute(hgemm<3,false,false,__half>, cudaFuncAttributeMaxDynamicSharedMemorySize, SMEMB);
    cudaFuncSetAttribute(hgemm<0,false,false,__half>, cudaFuncAttributeMaxDynamicSharedMemorySize, SMEMB);
    cudaFuncSetAttribute(hgemm<1,true ,false,__half>, cudaFuncAttributeMaxDynamicSharedMemorySize, SMEMB);
    cudaFuncSetAttribute(hgemm<2,false,true ,__half>, cudaFuncAttributeMaxDynamicSharedMemorySize, SMEMB);
    cudaFuncSetAttribute(hgemm<0,false,false,float >, cudaFuncAttributeMaxDynamicSharedMemorySize, SMEMB);

    // 1) prep: all conversions + rsum zero
    prep_all<<<(N4_TOT + 255)/256, 256>>>(x, wq, wkv_a, wkv_b, wo,
                                          xh, wqkh, wbh, woh, rsum);

    // 2) [q | kv] = x @ [wq ; wkv_a].T with inline q_pe RoPE (EPI=3)
    hgemm<3,false,false,__half><<<dim3(23,64,1),256,SMEMB>>>(xh, wqkh, qkraw,
        MTOT, QKW, DIM_, DIM_, DIM_, QKW,
        1, 0,0, 0,0, 0,0, 1.f, nullptr, 0, freqs);

    // 3) kcat[:,0:512] = rmsnorm(kv_c); k_pe roped + scattered into kcath x12
    rmsnorm_rope_k_kernel<<<MTOT,128>>>(qkraw, knw, freqs, kcat, kcath);

    // 4) kcath[b,h,:, :128] = kv_c @ Wb_nope_h^T
    hgemm<0,false,false,__half><<<dim3(1,16,BB*NH_),256,SMEMB>>>(kcat, wbh, kcath,
        SEQ, NOPE_, KVR_, KCATW, KVR_, HD2,
        NH_,
        (long long)SEQ*KCATW,    0,
        0,                       (long long)256*KVR_,
        (long long)NH_*SEQ*HD2,  (long long)SEQ*HD2,
        1.f, nullptr, 0, nullptr);

    // 5) vT[b,h] = Wb_v_h @ kv_c^T
    hgemm<0,false,false,__half><<<dim3(16,1,BB*NH_),256,SMEMB>>>(
        wbh + (long long)NOPE_*KVR_, kcat, vT,
        VH_, SEQ, KVR_, KVR_, KCATW, SEQ,
        NH_,
        0,                       (long long)256*KVR_,
        (long long)SEQ*KCATW,    0,
        (long long)NH_*VH_*SEQ,  (long long)VH_*SEQ,
        1.f, nullptr, 0, nullptr);

    // 6) P = exp2(SM_SCALE*log2e * q_h @ kcath^T) causal + row sums
    hgemm<1,true,false,__half><<<dim3(16,16,BB*NH_),256,SMEMB>>>(qkraw, kcath, scores,
        SEQ, SEQ, HD2, QKW, HD2, SEQ,
        NH_,
        (long long)SEQ*QKW,      (long long)QKH_,
        (long long)NH_*SEQ*HD2,  (long long)SEQ*HD2,
        (long long)NH_*SEQ*SEQ,  (long long)SEQ*SEQ,
        SM_SCALE_L2E, rsum, SEQ, nullptr);

    // 7) o2[b,s,h,:] = (P @ vT_h^T) / rowsum   (causal K-limit)
    hgemm<2,false,true,__half><<<dim3(1,16,BB*NH_),256,SMEMB>>>(scores, vT, o2,
        SEQ, VH_, SEQ, SEQ, SEQ, NH_*VH_,
        NH_,
        (long long)NH_*SEQ*SEQ,  (long long)SEQ*SEQ,
        (long long)NH_*VH_*SEQ,  (long long)VH_*SEQ,
        (long long)SEQ*NH_*VH_,  (long long)VH_,
        1.f, rsum, SEQ, nullptr);

    // 8) out = o2 @ wo.T   (fp32 output)
    hgemm<0,false,false,float><<<dim3(8,64,1),256,SMEMB>>>(o2, woh, out,
        MTOT, DIM_, NH_*VH_, NH_*VH_, NH_*VH_, DIM_,
        1, 0,0, 0,0, 0,0, 1.f, nullptr, 0, nullptr);
}